// round 11
// baseline (speedup 1.0000x reference)
#include <cuda_runtime.h>
#include <cuda_bf16.h>
#include <cstdint>

#define Bq 4
#define Vq 50000
#define Cq 160
#define V_CTA 64          // vertices per CTA (4 m16 tiles)
#define NTHR 256          // 8 warps: 4 m-tiles x 2 K-halves
#define KS 10             // 160 / 16
#define KH 5              // ksteps per K-half
#define NT 6              // 48 / 8
#define SB_U32 (KS * NT * 32 * 4)     // 7680 u32 = 30720B (B frags)
#define SMEM_BYTES (SB_U32 * 4)       // D scratch (64*49*4=12544B) aliases in

// B operand fragments in gmem: u32 [ks][nt][lane][4] = (bhi0,bhi1,blo0,blo1)
// k-permutation: thread t of the mma owns ACTUAL k = ks*16 + 4t .. 4t+3.
__device__ __align__(16) unsigned int g_bfrag[SB_U32];

// ---------------- Precompute: G -> permuted .col B fragments (bf16 hi/lo) ---
__global__ void precompute_kernel(const float* __restrict__ X,
                                  const float* __restrict__ Vn,
                                  const float* __restrict__ r6,
                                  const int* __restrict__ idx) {
    int i = blockIdx.x * blockDim.x + threadIdx.x;
    if (i >= Bq * Cq) return;
    int b = i / Cq, c = i % Cq;

    const float* d6 = r6 + (size_t)(b * Cq + c) * 6;
    float a1x = d6[0], a1y = d6[1], a1z = d6[2];
    float a2x = d6[3], a2y = d6[4], a2z = d6[5];

    float n1 = fmaxf(sqrtf(a1x*a1x + a1y*a1y + a1z*a1z), 1e-8f);
    float b1x = a1x/n1, b1y = a1y/n1, b1z = a1z/n1;
    float dt = b1x*a2x + b1y*a2y + b1z*a2z;
    float px = a2x - dt*b1x, py = a2y - dt*b1y, pz = a2z - dt*b1z;
    float n2 = fmaxf(sqrtf(px*px + py*py + pz*pz), 1e-8f);
    float b2x = px/n2, b2y = py/n2, b2z = pz/n2;
    float b3x = b1y*b2z - b1z*b2y;
    float b3y = b1z*b2x - b1x*b2z;
    float b3z = b1x*b2y - b1y*b2x;

    float R[3][3] = {{b1x,b1y,b1z},{b2x,b2y,b2z},{b3x,b3y,b3z}};

    int vi = idx[c];
    vi = max(0, min(Vq - 1, vi));
    const float* xc = X + ((size_t)b * Vq + vi) * 3;
    float cen[3] = {xc[0], xc[1], xc[2]};
    const float* vn = Vn + (size_t)(b * Cq + c) * 3;

    float g[12];
    #pragma unroll
    for (int k = 0; k < 3; k++) {
        #pragma unroll
        for (int d = 0; d < 3; d++) g[k*3 + d] = R[k][d];
        g[9 + k] = cen[k] + vn[k]
                 - (R[k][0]*cen[0] + R[k][1]*cen[1] + R[k][2]*cen[2]);
    }

    int ks  = c >> 4, klo = c & 15;
    int t   = klo >> 2;
    int j   = klo & 3;
    int reg = j >> 1;
    int elem = j & 1;
    unsigned short* p16 = (unsigned short*)g_bfrag;

    #pragma unroll
    for (int jj = 0; jj < 12; jj++) {
        int n = jj * 4 + b;
        int lane = (n & 7) * 4 + t;
        int slot = ((ks * NT + (n >> 3)) * 32 + lane) * 4;
        __nv_bfloat16 hi = __float2bfloat16_rn(g[jj]);
        __nv_bfloat16 lo = __float2bfloat16_rn(g[jj] - __bfloat162float(hi));
        p16[(slot + reg)     * 2 + elem] = __bfloat16_as_ushort(hi);
        p16[(slot + 2 + reg) * 2 + elem] = __bfloat16_as_ushort(lo);
    }
}

// ---------------- helpers ----------------
__device__ __forceinline__ uint32_t pack_bf16x2(float lo, float hi) {
    uint32_t r;
    asm("cvt.rn.bf16x2.f32 %0, %1, %2;" : "=r"(r) : "f"(hi), "f"(lo));
    return r;
}
__device__ __forceinline__ void mma16816(float* d, const uint32_t* a,
                                         uint32_t b0, uint32_t b1) {
    asm volatile(
        "mma.sync.aligned.m16n8k16.row.col.f32.bf16.bf16.f32 "
        "{%0,%1,%2,%3}, {%4,%5,%6,%7}, {%8,%9}, {%0,%1,%2,%3};"
        : "+f"(d[0]), "+f"(d[1]), "+f"(d[2]), "+f"(d[3])
        : "r"(a[0]), "r"(a[1]), "r"(a[2]), "r"(a[3]), "r"(b0), "r"(b1));
}
__device__ __forceinline__ void split4(float4 w, uint32_t& h01, uint32_t& h23,
                                       uint32_t& l01, uint32_t& l23) {
    h01 = pack_bf16x2(w.x, w.y);
    float hx = __uint_as_float(h01 << 16);
    float hy = __uint_as_float(h01 & 0xFFFF0000u);
    l01 = pack_bf16x2(w.x - hx, w.y - hy);
    h23 = pack_bf16x2(w.z, w.w);
    float hz = __uint_as_float(h23 << 16);
    float hw = __uint_as_float(h23 & 0xFFFF0000u);
    l23 = pack_bf16x2(w.z - hz, w.w - hw);
}

// ---------------- Main kernel: m16 per warp, K split across warp halves -----
__global__ void __launch_bounds__(NTHR, 3)
main_kernel(const float* __restrict__ W,
            const float* __restrict__ X,
            float* __restrict__ out) {
    extern __shared__ __align__(16) unsigned int smem[];
    unsigned int* sB = smem;

    int tid = threadIdx.x, wid = tid >> 5, lane = tid & 31;
    int g = lane >> 2, t = lane & 3;
    int mt = wid & 3;          // m16 tile (rows mt*16 .. mt*16+15)
    int kh = wid >> 2;         // K-half (ksteps kh*5 .. kh*5+4)
    int vbase = blockIdx.x * V_CTA;

    int r0 = min(vbase + mt * 16 + g,     Vq - 1);
    int r1 = min(vbase + mt * 16 + g + 8, Vq - 1);
    const float* w0p = W + (size_t)r0 * Cq + kh * (KH * 16) + 4 * t;
    const float* w1p = W + (size_t)r1 * Cq + kh * (KH * 16) + 4 * t;

    // Prefetch first kstep of this K-half (fires LDGs before B copy)
    float4 wa = *(const float4*)w0p;
    float4 wb = *(const float4*)w1p;

    // Copy B fragments to smem (30720B)
    {
        const uint4* src = (const uint4*)g_bfrag;
        uint4* dst = (uint4*)sB;
        #pragma unroll
        for (int i = tid; i < SB_U32 / 4; i += NTHR) dst[i] = src[i];
    }
    __syncthreads();

    float d[NT][4];
    #pragma unroll
    for (int nt = 0; nt < NT; nt++)
        #pragma unroll
        for (int r = 0; r < 4; r++) d[nt][r] = 0.0f;

    #pragma unroll
    for (int i = 0; i < KH; i++) {
        int ksg = kh * KH + i;
        float4 na, nb;
        if (i + 1 < KH) {
            na = *(const float4*)(w0p + (i + 1) * 16);
            nb = *(const float4*)(w1p + (i + 1) * 16);
        }
        uint32_t ah[4], al[4];
        split4(wa, ah[0], ah[2], al[0], al[2]);   // row g
        split4(wb, ah[1], ah[3], al[1], al[3]);   // row g+8
        #pragma unroll
        for (int nt = 0; nt < NT; nt++) {
            uint4 bb = *(const uint4*)&sB[((ksg * NT + nt) * 32 + lane) * 4];
            mma16816(d[nt], ah, bb.x, bb.y);   // hi*hi
            mma16816(d[nt], ah, bb.z, bb.w);   // hi*lo
            mma16816(d[nt], al, bb.x, bb.y);   // lo*hi
        }
        wa = na; wb = nb;
    }

    // ---- combine K-halves in smem D scratch [64][49] (aliases sB) ----
    __syncthreads();                 // everyone done reading sB
    float* Dsm = (float*)sB;
    if (kh == 0) {
        #pragma unroll
        for (int nt = 0; nt < NT; nt++) {
            int col = nt * 8 + 2 * t;
            int q0 = (mt * 16 + g) * 49, q1 = (mt * 16 + g + 8) * 49;
            Dsm[q0 + col] = d[nt][0]; Dsm[q0 + col + 1] = d[nt][1];
            Dsm[q1 + col] = d[nt][2]; Dsm[q1 + col + 1] = d[nt][3];
        }
    }
    __syncthreads();
    if (kh == 1) {
        #pragma unroll
        for (int nt = 0; nt < NT; nt++) {
            int col = nt * 8 + 2 * t;
            int q0 = (mt * 16 + g) * 49, q1 = (mt * 16 + g + 8) * 49;
            Dsm[q0 + col]     += d[nt][0];
            Dsm[q0 + col + 1] += d[nt][1];
            Dsm[q1 + col]     += d[nt][2];
            Dsm[q1 + col + 1] += d[nt][3];
        }
    }
    __syncthreads();

    // Epilogue: thread = (vertex, batch); 256 = 64 x 4 exactly
    int vl = tid >> 2, b = tid & 3;
    int v = vbase + vl;
    if (v < Vq) {
        float m[12];
        #pragma unroll
        for (int j = 0; j < 12; j++) m[j] = Dsm[vl * 49 + j * 4 + b];
        const float* xp = X + ((size_t)b * Vq + v) * 3;
        float x0 = xp[0], x1 = xp[1], x2 = xp[2];
        float* op = out + ((size_t)b * Vq + v) * 3;
        op[0] = m[9]  + m[0]*x0 + m[1]*x1 + m[2]*x2;
        op[1] = m[10] + m[3]*x0 + m[4]*x1 + m[5]*x2;
        op[2] = m[11] + m[6]*x0 + m[7]*x1 + m[8]*x2;
    }
}

// ---------------- launch ----------------
extern "C" void kernel_launch(void* const* d_in, const int* in_sizes, int n_in,
                              void* d_out, int out_size) {
    const float* X   = (const float*)d_in[0];
    const float* Vn  = (const float*)d_in[1];
    const float* r6  = (const float*)d_in[2];
    const float* W   = (const float*)d_in[3];
    const int*   idx = (const int*)d_in[4];   // JAX x64-disabled: int64 -> int32
    float* out = (float*)d_out;

    precompute_kernel<<<(Bq * Cq + 127) / 128, 128>>>(X, Vn, r6, idx);

    cudaFuncSetAttribute(main_kernel,
                         cudaFuncAttributeMaxDynamicSharedMemorySize, SMEM_BYTES);
    int grid = (Vq + V_CTA - 1) / V_CTA;    // 782
    main_kernel<<<grid, NTHR, SMEM_BYTES>>>(W, X, out);
}

// round 12
// speedup vs baseline: 1.1686x; 1.1686x over previous
#include <cuda_runtime.h>
#include <cuda_bf16.h>
#include <cstdint>

#define Bq 4
#define Vq 50000
#define Cq 160
#define V_CTA 128         // vertices per CTA (4 warps x m32)
#define NTHR 128
#define KS 10             // 160 / 16
#define NT 6              // 48 / 8
#define SB_U32 (KS * NT * 32 * 4)     // 7680 u32 = 30720B
#define SMEM_BYTES (SB_U32 * 4)       // >= 128*49*4 D scratch

// B operand fragments in gmem: u32 [ks][nt][lane][4] = (bhi0,bhi1,blo0,blo1)
// k-permutation: thread t of the mma owns ACTUAL k = ks*16 + 4t .. 4t+3.
__device__ __align__(16) unsigned int g_bfrag[SB_U32];

// ---------------- Precompute: G -> permuted .col B fragments (bf16 hi/lo) ---
__global__ void precompute_kernel(const float* __restrict__ X,
                                  const float* __restrict__ Vn,
                                  const float* __restrict__ r6,
                                  const int* __restrict__ idx) {
    int i = blockIdx.x * blockDim.x + threadIdx.x;
    if (i >= Bq * Cq) return;
    int b = i / Cq, c = i % Cq;

    const float* d6 = r6 + (size_t)(b * Cq + c) * 6;
    float a1x = d6[0], a1y = d6[1], a1z = d6[2];
    float a2x = d6[3], a2y = d6[4], a2z = d6[5];

    float n1 = fmaxf(sqrtf(a1x*a1x + a1y*a1y + a1z*a1z), 1e-8f);
    float b1x = a1x/n1, b1y = a1y/n1, b1z = a1z/n1;
    float dt = b1x*a2x + b1y*a2y + b1z*a2z;
    float px = a2x - dt*b1x, py = a2y - dt*b1y, pz = a2z - dt*b1z;
    float n2 = fmaxf(sqrtf(px*px + py*py + pz*pz), 1e-8f);
    float b2x = px/n2, b2y = py/n2, b2z = pz/n2;
    float b3x = b1y*b2z - b1z*b2y;
    float b3y = b1z*b2x - b1x*b2z;
    float b3z = b1x*b2y - b1y*b2x;

    float R[3][3] = {{b1x,b1y,b1z},{b2x,b2y,b2z},{b3x,b3y,b3z}};

    int vi = idx[c];
    vi = max(0, min(Vq - 1, vi));
    const float* xc = X + ((size_t)b * Vq + vi) * 3;
    float cen[3] = {xc[0], xc[1], xc[2]};
    const float* vn = Vn + (size_t)(b * Cq + c) * 3;

    float g[12];
    #pragma unroll
    for (int k = 0; k < 3; k++) {
        #pragma unroll
        for (int d = 0; d < 3; d++) g[k*3 + d] = R[k][d];
        g[9 + k] = cen[k] + vn[k]
                 - (R[k][0]*cen[0] + R[k][1]*cen[1] + R[k][2]*cen[2]);
    }

    int ks  = c >> 4, klo = c & 15;
    int t   = klo >> 2;
    int j   = klo & 3;
    int reg = j >> 1;
    int elem = j & 1;
    unsigned short* p16 = (unsigned short*)g_bfrag;

    #pragma unroll
    for (int jj = 0; jj < 12; jj++) {
        int n = jj * 4 + b;
        int lane = (n & 7) * 4 + t;
        int slot = ((ks * NT + (n >> 3)) * 32 + lane) * 4;
        __nv_bfloat16 hi = __float2bfloat16_rn(g[jj]);
        __nv_bfloat16 lo = __float2bfloat16_rn(g[jj] - __bfloat162float(hi));
        p16[(slot + reg)     * 2 + elem] = __bfloat16_as_ushort(hi);
        p16[(slot + 2 + reg) * 2 + elem] = __bfloat16_as_ushort(lo);
    }
}

// ---------------- helpers ----------------
__device__ __forceinline__ uint32_t pack_bf16x2(float lo, float hi) {
    uint32_t r;
    asm("cvt.rn.bf16x2.f32 %0, %1, %2;" : "=r"(r) : "f"(hi), "f"(lo));
    return r;
}
// NOTE: no volatile -> ptxas may schedule freely around these
__device__ __forceinline__ void mma16816(float* d, const uint32_t* a,
                                         uint32_t b0, uint32_t b1) {
    asm("mma.sync.aligned.m16n8k16.row.col.f32.bf16.bf16.f32 "
        "{%0,%1,%2,%3}, {%4,%5,%6,%7}, {%8,%9}, {%0,%1,%2,%3};"
        : "+f"(d[0]), "+f"(d[1]), "+f"(d[2]), "+f"(d[3])
        : "r"(a[0]), "r"(a[1]), "r"(a[2]), "r"(a[3]), "r"(b0), "r"(b1));
}
__device__ __forceinline__ void split4(float4 w, uint32_t& h01, uint32_t& h23,
                                       uint32_t& l01, uint32_t& l23) {
    h01 = pack_bf16x2(w.x, w.y);
    float hx = __uint_as_float(h01 << 16);
    float hy = __uint_as_float(h01 & 0xFFFF0000u);
    l01 = pack_bf16x2(w.x - hx, w.y - hy);
    h23 = pack_bf16x2(w.z, w.w);
    float hz = __uint_as_float(h23 << 16);
    float hw = __uint_as_float(h23 & 0xFFFF0000u);
    l23 = pack_bf16x2(w.z - hz, w.w - hw);
}

// ---------------- Main kernel: m32 per warp, pass-major MMA ordering --------
__global__ void __launch_bounds__(NTHR, 3)
main_kernel(const float* __restrict__ W,
            const float* __restrict__ X,
            float* __restrict__ out) {
    extern __shared__ __align__(16) unsigned int smem[];
    unsigned int* sB = smem;

    int tid = threadIdx.x, wid = tid >> 5, lane = tid & 31;
    int g = lane >> 2, t = lane & 3;
    int vbase = blockIdx.x * V_CTA;

    // 4 fragment row-groups per warp: g, g+8 (tile0), g+16, g+24 (tile1)
    const float* wp[4];
    #pragma unroll
    for (int i = 0; i < 4; i++) {
        int r = min(vbase + wid * 32 + g + 8 * i, Vq - 1);
        wp[i] = W + (size_t)r * Cq + 4 * t;
    }

    // Prefetch kstep 0
    float4 cur0 = *(const float4*)wp[0];
    float4 cur1 = *(const float4*)wp[1];
    float4 cur2 = *(const float4*)wp[2];
    float4 cur3 = *(const float4*)wp[3];

    // Copy B fragments to smem (30720B)
    {
        const uint4* src = (const uint4*)g_bfrag;
        uint4* dst = (uint4*)sB;
        #pragma unroll
        for (int i = tid; i < SB_U32 / 4; i += NTHR) dst[i] = src[i];
    }
    __syncthreads();

    float d0[NT][4], d1[NT][4];
    #pragma unroll
    for (int nt = 0; nt < NT; nt++)
        #pragma unroll
        for (int r = 0; r < 4; r++) { d0[nt][r] = 0.0f; d1[nt][r] = 0.0f; }

    #pragma unroll
    for (int ks = 0; ks < KS; ks++) {
        float4 n0, n1, n2, n3;
        if (ks + 1 < KS) {
            n0 = *(const float4*)(wp[0] + (ks + 1) * 16);
            n1 = *(const float4*)(wp[1] + (ks + 1) * 16);
            n2 = *(const float4*)(wp[2] + (ks + 1) * 16);
            n3 = *(const float4*)(wp[3] + (ks + 1) * 16);
        }
        uint32_t ah0[4], al0[4], ah1[4], al1[4];
        split4(cur0, ah0[0], ah0[2], al0[0], al0[2]);
        split4(cur1, ah0[1], ah0[3], al0[1], al0[3]);
        split4(cur2, ah1[0], ah1[2], al1[0], al1[2]);
        split4(cur3, ah1[1], ah1[3], al1[1], al1[3]);

        // load all B fragments for this kstep first
        uint4 bb[NT];
        #pragma unroll
        for (int nt = 0; nt < NT; nt++)
            bb[nt] = *(const uint4*)&sB[((ks * NT + nt) * 32 + lane) * 4];

        // pass-major: dependency distance on each accumulator = 12 MMAs
        #pragma unroll
        for (int nt = 0; nt < NT; nt++) {          // pass 0: hi*hi
            mma16816(d0[nt], ah0, bb[nt].x, bb[nt].y);
            mma16816(d1[nt], ah1, bb[nt].x, bb[nt].y);
        }
        #pragma unroll
        for (int nt = 0; nt < NT; nt++) {          // pass 1: hi*lo
            mma16816(d0[nt], ah0, bb[nt].z, bb[nt].w);
            mma16816(d1[nt], ah1, bb[nt].z, bb[nt].w);
        }
        #pragma unroll
        for (int nt = 0; nt < NT; nt++) {          // pass 2: lo*hi
            mma16816(d0[nt], al0, bb[nt].x, bb[nt].y);
            mma16816(d1[nt], al1, bb[nt].x, bb[nt].y);
        }
        cur0 = n0; cur1 = n1; cur2 = n2; cur3 = n3;
    }

    __syncthreads();   // done reading sB; reuse as D scratch [128][49]
    float* Dsm = (float*)sB;
    #pragma unroll
    for (int nt = 0; nt < NT; nt++) {
        int col = nt * 8 + 2 * t;
        int q0 = (wid * 32 + g) * 49;
        int q1 = (wid * 32 + g + 8) * 49;
        int q2 = (wid * 32 + g + 16) * 49;
        int q3 = (wid * 32 + g + 24) * 49;
        Dsm[q0 + col] = d0[nt][0]; Dsm[q0 + col + 1] = d0[nt][1];
        Dsm[q1 + col] = d0[nt][2]; Dsm[q1 + col + 1] = d0[nt][3];
        Dsm[q2 + col] = d1[nt][0]; Dsm[q2 + col + 1] = d1[nt][1];
        Dsm[q3 + col] = d1[nt][2]; Dsm[q3 + col + 1] = d1[nt][3];
    }
    __syncthreads();

    // Epilogue: thread tid owns vertex vbase+tid, all 4 batches
    int v = vbase + tid;
    if (v < Vq) {
        float m[12];
        #pragma unroll
        for (int b = 0; b < Bq; b++) {
            #pragma unroll
            for (int j = 0; j < 12; j++) m[j] = Dsm[tid * 49 + j * 4 + b];
            const float* xp = X + ((size_t)b * Vq + v) * 3;
            float x0 = xp[0], x1 = xp[1], x2 = xp[2];
            float* op = out + ((size_t)b * Vq + v) * 3;
            op[0] = m[9]  + m[0]*x0 + m[1]*x1 + m[2]*x2;
            op[1] = m[10] + m[3]*x0 + m[4]*x1 + m[5]*x2;
            op[2] = m[11] + m[6]*x0 + m[7]*x1 + m[8]*x2;
        }
    }
}

// ---------------- launch ----------------
extern "C" void kernel_launch(void* const* d_in, const int* in_sizes, int n_in,
                              void* d_out, int out_size) {
    const float* X   = (const float*)d_in[0];
    const float* Vn  = (const float*)d_in[1];
    const float* r6  = (const float*)d_in[2];
    const float* W   = (const float*)d_in[3];
    const int*   idx = (const int*)d_in[4];   // JAX x64-disabled: int64 -> int32
    float* out = (float*)d_out;

    precompute_kernel<<<(Bq * Cq + 127) / 128, 128>>>(X, Vn, r6, idx);

    cudaFuncSetAttribute(main_kernel,
                         cudaFuncAttributeMaxDynamicSharedMemorySize, SMEM_BYTES);
    int grid = (Vq + V_CTA - 1) / V_CTA;    // 391
    main_kernel<<<grid, NTHR, SMEM_BYTES>>>(W, X, out);
}